// round 5
// baseline (speedup 1.0000x reference)
#include <cuda_runtime.h>
#include <math.h>

#define BN 8192
#define CN 1024
#define APC 8   // anchors per class = BN/CN

// Scratch (device globals — no allocation allowed)
__device__ float g_lse[BN];
__device__ int g_first0[CN];
__device__ int g_first1[CN];
__device__ int g_anchor[CN * APC];
__device__ unsigned long long g_negkey[CN];
__device__ float g_rowloss[BN];

__device__ __forceinline__ unsigned long long packkey(float f, int j) {
    unsigned u = __float_as_uint(f);
    u = (u & 0x80000000u) ? ~u : (u | 0x80000000u);  // monotone float -> uint
    return ((unsigned long long)u << 32) | (unsigned)j;
}

// Single block, 1024 threads: init negkey, compute first0/first1 per class,
// and record the APC anchor indices of each class (slot order arbitrary —
// per-anchor results are order-independent).
__global__ void k_pos(const int* __restrict__ tgt) {
    __shared__ int s_f0[CN];
    __shared__ int s_f1[CN];
    __shared__ int s_cnt[CN];
    int tid = threadIdx.x;
    s_f0[tid] = 0x7fffffff;
    s_f1[tid] = 0x7fffffff;
    s_cnt[tid] = 0;
    g_negkey[tid] = ~0ull;
    __syncthreads();
#pragma unroll
    for (int k = 0; k < BN / 1024; k++) {
        int j = k * 1024 + tid;
        atomicMin(&s_f0[tgt[j]], j);
    }
    __syncthreads();
#pragma unroll
    for (int k = 0; k < BN / 1024; k++) {
        int j = k * 1024 + tid;
        int t = tgt[j];
        if (j != s_f0[t]) atomicMin(&s_f1[t], j);
        int slot = atomicAdd(&s_cnt[t], 1);
        if (slot < APC) g_anchor[t * APC + slot] = j;
    }
    __syncthreads();
    g_first0[tid] = s_f0[tid];
    g_first1[tid] = s_f1[tid];
}

// One warp per row, float4 loads: lse_j = max + log(sum exp(x - max))
__global__ void k_lse(const float* __restrict__ x) {
    int warp = (blockIdx.x * blockDim.x + threadIdx.x) >> 5;
    int lane = threadIdx.x & 31;
    if (warp >= BN) return;
    const float4* row = reinterpret_cast<const float4*>(x + (size_t)warp * CN);
    float4 v[8];
    float m = -INFINITY;
#pragma unroll
    for (int k = 0; k < 8; k++) {
        v[k] = row[k * 32 + lane];
        m = fmaxf(m, fmaxf(fmaxf(v[k].x, v[k].y), fmaxf(v[k].z, v[k].w)));
    }
#pragma unroll
    for (int o = 16; o > 0; o >>= 1) m = fmaxf(m, __shfl_xor_sync(0xffffffffu, m, o));
    float s = 0.f;
#pragma unroll
    for (int k = 0; k < 8; k++) {
        s += __expf(v[k].x - m) + __expf(v[k].y - m)
           + __expf(v[k].z - m) + __expf(v[k].w - m);
    }
#pragma unroll
    for (int o = 16; o > 0; o >>= 1) s += __shfl_xor_sync(0xffffffffu, s, o);
    if (lane == 0) g_lse[warp] = m + __logf(s);
}

// Column-wise argmin of (x[j,c] - lse_j), excluding rows with target[j]==c.
// Grid: 512 blocks x 256 threads. Block b covers rows [b*16, b*16+16), all 1024 cols.
__global__ void k_neg(const float* __restrict__ x, const int* __restrict__ tgt) {
    __shared__ float s_lse[16];
    __shared__ int s_tgt[16];
    int tid = threadIdx.x;
    int r0 = blockIdx.x * 16;
    if (tid < 16) {
        s_lse[tid] = g_lse[r0 + tid];
        s_tgt[tid] = tgt[r0 + tid];
    }
    __syncthreads();

    int c0 = tid * 4;
    float bh0 = INFINITY, bh1 = INFINITY, bh2 = INFINITY, bh3 = INFINITY;
    int bj0 = 0, bj1 = 0, bj2 = 0, bj3 = 0;

#pragma unroll 4
    for (int jj = 0; jj < 16; jj++) {
        int j = r0 + jj;
        float4 v = *reinterpret_cast<const float4*>(x + (size_t)j * CN + c0);
        float ls = s_lse[jj];
        int tj = s_tgt[jj];
        float h0 = v.x - ls, h1 = v.y - ls, h2 = v.z - ls, h3 = v.w - ls;
        if (tj == c0) h0 = INFINITY;
        else if (tj == c0 + 1) h1 = INFINITY;
        else if (tj == c0 + 2) h2 = INFINITY;
        else if (tj == c0 + 3) h3 = INFINITY;
        if (h0 < bh0) { bh0 = h0; bj0 = j; }
        if (h1 < bh1) { bh1 = h1; bj1 = j; }
        if (h2 < bh2) { bh2 = h2; bj2 = j; }
        if (h3 < bh3) { bh3 = h3; bj3 = j; }
    }
    atomicMin(&g_negkey[c0 + 0], packkey(bh0, bj0));
    atomicMin(&g_negkey[c0 + 1], packkey(bh1, bj1));
    atomicMin(&g_negkey[c0 + 2], packkey(bh2, bj2));
    atomicMin(&g_negkey[c0 + 3], packkey(bh3, bj3));
}

// Block-per-class loss: block c stages s0 = x_f0 + x_n and s1 = x_f1 + x_n
// in smem, then warp w handles anchor g_anchor[c*APC+w]:
// loss_i = lse(x_i + s?) - (x_i + s?)[c]
__global__ void k_loss(const float* __restrict__ x) {
    __shared__ float s0[CN];
    __shared__ float s1[CN];
    int c = blockIdx.x;
    int tid = threadIdx.x;
    int f0 = g_first0[c];
    int f1 = g_first1[c];
    int n = (int)(g_negkey[c] & 0xffffffffull);

    // Stage: 256 threads x 1 float4 each per row
    {
        float4 a = reinterpret_cast<const float4*>(x + (size_t)f0 * CN)[tid];
        float4 b = reinterpret_cast<const float4*>(x + (size_t)f1 * CN)[tid];
        float4 d = reinterpret_cast<const float4*>(x + (size_t)n * CN)[tid];
        float4 u, w;
        u.x = a.x + d.x; u.y = a.y + d.y; u.z = a.z + d.z; u.w = a.w + d.w;
        w.x = b.x + d.x; w.y = b.y + d.y; w.z = b.z + d.z; w.w = b.w + d.w;
        reinterpret_cast<float4*>(s0)[tid] = u;
        reinterpret_cast<float4*>(s1)[tid] = w;
    }
    __syncthreads();

    int wid = tid >> 5, lane = tid & 31;
    int i = g_anchor[c * APC + wid];
    const float4* xi = reinterpret_cast<const float4*>(x + (size_t)i * CN);
    const float4* sp = reinterpret_cast<const float4*>((i == f0) ? s1 : s0);

    float4 s4[8];
    float m = -INFINITY;
    float st = 0.f;
#pragma unroll
    for (int k = 0; k < 8; k++) {
        int q = k * 32 + lane;            // float4 index; covers cols [4q, 4q+4)
        float4 a = xi[q];
        float4 b = sp[q];
        float4 v;
        v.x = a.x + b.x;
        v.y = a.y + b.y;
        v.z = a.z + b.z;
        v.w = a.w + b.w;
        s4[k] = v;
        m = fmaxf(m, fmaxf(fmaxf(v.x, v.y), fmaxf(v.z, v.w)));
        if ((c >> 2) == q) {
            int e = c & 3;
            st = (e == 0) ? v.x : (e == 1) ? v.y : (e == 2) ? v.z : v.w;
        }
    }
#pragma unroll
    for (int o = 16; o > 0; o >>= 1) m = fmaxf(m, __shfl_xor_sync(0xffffffffu, m, o));
    float sum = 0.f;
#pragma unroll
    for (int k = 0; k < 8; k++) {
        float4 v = s4[k];
        sum += __expf(v.x - m) + __expf(v.y - m)
             + __expf(v.z - m) + __expf(v.w - m);
    }
#pragma unroll
    for (int o = 16; o > 0; o >>= 1) sum += __shfl_xor_sync(0xffffffffu, sum, o);
    float stv = __shfl_sync(0xffffffffu, st, (c >> 2) & 31);
    if (lane == 0) g_rowloss[i] = (m + __logf(sum)) - stv;
}

// Deterministic final reduce: one block, fixed tree.
__global__ void k_final(float* __restrict__ out) {
    __shared__ float sh[256];
    float s = 0.f;
    for (int k = threadIdx.x; k < BN; k += 256) s += g_rowloss[k];
    sh[threadIdx.x] = s;
    __syncthreads();
    for (int o = 128; o > 0; o >>= 1) {
        if (threadIdx.x < o) sh[threadIdx.x] += sh[threadIdx.x + o];
        __syncthreads();
    }
    if (threadIdx.x == 0) out[0] = sh[0] / (float)BN;
}

extern "C" void kernel_launch(void* const* d_in, const int* in_sizes, int n_in,
                              void* d_out, int out_size) {
    const float* x = (const float*)d_in[0];
    const int* tgt = (const int*)d_in[1];
    float* out = (float*)d_out;
    (void)in_sizes; (void)n_in; (void)out_size;

    k_pos<<<1, 1024>>>(tgt);
    k_lse<<<BN / 8, 256>>>(x);          // 8 warps/block, warp per row
    k_neg<<<BN / 16, 256>>>(x, tgt);    // 512 blocks, 16 rows each
    k_loss<<<CN, 256>>>(x);             // block per class
    k_final<<<1, 256>>>(out);
}

// round 6
// speedup vs baseline: 1.3270x; 1.3270x over previous
#include <cuda_runtime.h>
#include <math.h>

#define BN 8192
#define CN 1024
#define APC 8   // anchors per class = BN/CN

// Scratch (device globals — no allocation allowed)
__device__ int g_first0[CN];
__device__ int g_first1[CN];
__device__ int g_anchor[CN * APC];
__device__ unsigned long long g_negkey[CN];
__device__ float g_rowloss[BN];

__device__ __forceinline__ unsigned long long packkey(float f, int j) {
    unsigned u = __float_as_uint(f);
    u = (u & 0x80000000u) ? ~u : (u | 0x80000000u);  // monotone float -> uint
    return ((unsigned long long)u << 32) | (unsigned)j;
}

__device__ __forceinline__ float max4(float4 v) {
    return fmaxf(fmaxf(v.x, v.y), fmaxf(v.z, v.w));
}

// Single block, 1024 threads: init negkey, compute first0/first1 per class,
// and record the APC anchor indices of each class (slot order arbitrary —
// per-anchor loss values and their write addresses are order-independent).
__global__ void k_pos(const int* __restrict__ tgt) {
    __shared__ int s_f0[CN];
    __shared__ int s_f1[CN];
    __shared__ int s_cnt[CN];
    int tid = threadIdx.x;
    s_f0[tid] = 0x7fffffff;
    s_f1[tid] = 0x7fffffff;
    s_cnt[tid] = 0;
    g_negkey[tid] = ~0ull;
    __syncthreads();
#pragma unroll
    for (int k = 0; k < BN / 1024; k++) {
        int j = k * 1024 + tid;
        atomicMin(&s_f0[tgt[j]], j);
    }
    __syncthreads();
#pragma unroll
    for (int k = 0; k < BN / 1024; k++) {
        int j = k * 1024 + tid;
        int t = tgt[j];
        if (j != s_f0[t]) atomicMin(&s_f1[t], j);
        int slot = atomicAdd(&s_cnt[t], 1);
        if (slot < APC) g_anchor[t * APC + slot] = j;
    }
    __syncthreads();
    g_first0[tid] = s_f0[tid];
    g_first1[tid] = s_f1[tid];
}

// Fused LSE + column-argmin. Block b owns rows [b*32, b*32+32).
// Phase A: warp w computes lse of rows r0+4w..r0+4w+3 (online softmax).
// Phase B: column argmin of (x[j,c] - lse_j) over the 32 rows (rows re-read
// from L1), excluding target[j]==c; result merged into g_negkey via atomicMin.
__global__ void k_fused(const float* __restrict__ x, const int* __restrict__ tgt) {
    __shared__ float s_lse[32];
    __shared__ int s_tgt[32];
    int tid = threadIdx.x, wid = tid >> 5, lane = tid & 31;
    int r0 = blockIdx.x * 32;

    if (tid < 32) s_tgt[tid] = tgt[r0 + tid];

#pragma unroll
    for (int r = 0; r < 4; r++) {
        int row = r0 + wid * 4 + r;
        const float4* rp = reinterpret_cast<const float4*>(x + (size_t)row * CN);
        float4 v = rp[lane];
        float m = max4(v);
        float s = __expf(v.x - m) + __expf(v.y - m) + __expf(v.z - m) + __expf(v.w - m);
#pragma unroll
        for (int k = 1; k < 8; k++) {
            v = rp[k * 32 + lane];
            float cm = max4(v);
            if (cm > m) { s *= __expf(m - cm); m = cm; }
            s += __expf(v.x - m) + __expf(v.y - m) + __expf(v.z - m) + __expf(v.w - m);
        }
#pragma unroll
        for (int o = 16; o > 0; o >>= 1) {
            float mo = __shfl_xor_sync(0xffffffffu, m, o);
            float so = __shfl_xor_sync(0xffffffffu, s, o);
            float nm = fmaxf(m, mo);
            s = s * __expf(m - nm) + so * __expf(mo - nm);
            m = nm;
        }
        if (lane == 0) s_lse[wid * 4 + r] = m + __logf(s);
    }
    __syncthreads();

    int c0 = tid * 4;
    float bh0 = INFINITY, bh1 = INFINITY, bh2 = INFINITY, bh3 = INFINITY;
    int bj0 = 0, bj1 = 0, bj2 = 0, bj3 = 0;

#pragma unroll 4
    for (int jj = 0; jj < 32; jj++) {
        int j = r0 + jj;
        float4 v = *reinterpret_cast<const float4*>(x + (size_t)j * CN + c0);
        float ls = s_lse[jj];
        int tj = s_tgt[jj];
        float h0 = v.x - ls, h1 = v.y - ls, h2 = v.z - ls, h3 = v.w - ls;
        if (tj == c0) h0 = INFINITY;
        else if (tj == c0 + 1) h1 = INFINITY;
        else if (tj == c0 + 2) h2 = INFINITY;
        else if (tj == c0 + 3) h3 = INFINITY;
        if (h0 < bh0) { bh0 = h0; bj0 = j; }
        if (h1 < bh1) { bh1 = h1; bj1 = j; }
        if (h2 < bh2) { bh2 = h2; bj2 = j; }
        if (h3 < bh3) { bh3 = h3; bj3 = j; }
    }
    atomicMin(&g_negkey[c0 + 0], packkey(bh0, bj0));
    atomicMin(&g_negkey[c0 + 1], packkey(bh1, bj1));
    atomicMin(&g_negkey[c0 + 2], packkey(bh2, bj2));
    atomicMin(&g_negkey[c0 + 3], packkey(bh3, bj3));
}

// Block-per-class loss (online softmax): block c stages s0 = x_f0 + x_n and
// s1 = x_f1 + x_n in smem; warp w handles anchor g_anchor[c*APC+w]:
// loss_i = lse(x_i + s?) - (x_i + s?)[c]
__global__ void k_loss(const float* __restrict__ x) {
    __shared__ float s0[CN];
    __shared__ float s1[CN];
    int c = blockIdx.x;
    int tid = threadIdx.x;
    int f0 = g_first0[c];
    int f1 = g_first1[c];
    int n = (int)(g_negkey[c] & 0xffffffffull);

    {
        float4 a = reinterpret_cast<const float4*>(x + (size_t)f0 * CN)[tid];
        float4 b = reinterpret_cast<const float4*>(x + (size_t)f1 * CN)[tid];
        float4 d = reinterpret_cast<const float4*>(x + (size_t)n * CN)[tid];
        float4 u, w;
        u.x = a.x + d.x; u.y = a.y + d.y; u.z = a.z + d.z; u.w = a.w + d.w;
        w.x = b.x + d.x; w.y = b.y + d.y; w.z = b.z + d.z; w.w = b.w + d.w;
        reinterpret_cast<float4*>(s0)[tid] = u;
        reinterpret_cast<float4*>(s1)[tid] = w;
    }
    __syncthreads();

    int wid = tid >> 5, lane = tid & 31;
    int i = g_anchor[c * APC + wid];
    const float4* xi = reinterpret_cast<const float4*>(x + (size_t)i * CN);
    const float4* sp = reinterpret_cast<const float4*>((i == g_first0[c]) ? s1 : s0);

    float m, s, st = 0.f;
    {
        float4 a = xi[lane];
        float4 b = sp[lane];
        float4 v;
        v.x = a.x + b.x; v.y = a.y + b.y; v.z = a.z + b.z; v.w = a.w + b.w;
        m = max4(v);
        s = __expf(v.x - m) + __expf(v.y - m) + __expf(v.z - m) + __expf(v.w - m);
        if ((c >> 2) == lane) {
            int e = c & 3;
            st = (e == 0) ? v.x : (e == 1) ? v.y : (e == 2) ? v.z : v.w;
        }
    }
#pragma unroll
    for (int k = 1; k < 8; k++) {
        int q = k * 32 + lane;
        float4 a = xi[q];
        float4 b = sp[q];
        float4 v;
        v.x = a.x + b.x; v.y = a.y + b.y; v.z = a.z + b.z; v.w = a.w + b.w;
        float cm = max4(v);
        if (cm > m) { s *= __expf(m - cm); m = cm; }
        s += __expf(v.x - m) + __expf(v.y - m) + __expf(v.z - m) + __expf(v.w - m);
        if ((c >> 2) == q) {
            int e = c & 3;
            st = (e == 0) ? v.x : (e == 1) ? v.y : (e == 2) ? v.z : v.w;
        }
    }
#pragma unroll
    for (int o = 16; o > 0; o >>= 1) {
        float mo = __shfl_xor_sync(0xffffffffu, m, o);
        float so = __shfl_xor_sync(0xffffffffu, s, o);
        float nm = fmaxf(m, mo);
        s = s * __expf(m - nm) + so * __expf(mo - nm);
        m = nm;
    }
    float stv = __shfl_sync(0xffffffffu, st, (c >> 2) & 31);
    if (lane == 0) g_rowloss[i] = (m + __logf(s)) - stv;
}

// Deterministic final reduce: one block, fixed tree.
__global__ void k_final(float* __restrict__ out) {
    __shared__ float sh[256];
    float s = 0.f;
    for (int k = threadIdx.x; k < BN; k += 256) s += g_rowloss[k];
    sh[threadIdx.x] = s;
    __syncthreads();
    for (int o = 128; o > 0; o >>= 1) {
        if (threadIdx.x < o) sh[threadIdx.x] += sh[threadIdx.x + o];
        __syncthreads();
    }
    if (threadIdx.x == 0) out[0] = sh[0] / (float)BN;
}

extern "C" void kernel_launch(void* const* d_in, const int* in_sizes, int n_in,
                              void* d_out, int out_size) {
    const float* x = (const float*)d_in[0];
    const int* tgt = (const int*)d_in[1];
    float* out = (float*)d_out;
    (void)in_sizes; (void)n_in; (void)out_size;

    k_pos<<<1, 1024>>>(tgt);
    k_fused<<<BN / 32, 256>>>(x, tgt);  // 256 blocks: lse + column argmin
    k_loss<<<CN, 256>>>(x);             // block per class, online softmax
    k_final<<<1, 256>>>(out);
}